// round 15
// baseline (speedup 1.0000x reference)
#include <cuda_runtime.h>
#include <cuda_bf16.h>
#include <math.h>
#include <stdint.h>

#define ACT_NONE 0
#define ACT_RELU 1
#define ACT_SIG  2

// ---------------- fp32 scratch (encoder path + dec3 out) ----------------
__device__ float  g_a1[128 * 64 * 64 * 32];    // enc1 out / dec3 out
__device__ float  g_a2[128 * 32 * 32 * 64];    // enc2 out
__device__ float  g_a3[128 * 16 * 16 * 128];   // enc3 out
__device__ float  g_z [128 * 16 * 16 * 64];
__device__ int    g_idx[128 * 256];
__device__ float  g_e2[512];
__device__ double g_loss;

// ---------------- bf16 split planes (decoder path) ----------------
__device__ __nv_bfloat16 pqh[2097152],  pqm[2097152];   // q
__device__ __nv_bfloat16 d1h[4194304],  d1m[4194304];   // dec1 out
__device__ __nv_bfloat16 d2h[8388608],  d2m[8388608];   // dec2 out
__device__ __nv_bfloat16 wd1h[32768],  wd1m[32768];
__device__ __nv_bfloat16 wd2h[131072], wd2m[131072];
__device__ __nv_bfloat16 wd3h[32768],  wd3m[32768];

static const int Y_SIZE  = 128 * 128 * 128 * 3;
static const int N_POS   = 128 * 16 * 16;
static const int Z_ELEMS = N_POS * 64;

__host__ __device__ constexpr int ilog2c(int v) {
    int l = 0; while (v > 1) { v >>= 1; ++l; } return l;
}

__device__ __forceinline__ float actf(float v, int ACT) {
    if (ACT == ACT_RELU) return fmaxf(v, 0.0f);
    if (ACT == ACT_SIG)  return 1.0f / (1.0f + expf(-v));
    return v;
}

__device__ __forceinline__ void ffma2(unsigned long long& d,
                                      unsigned long long a, unsigned long long b) {
    asm("fma.rn.f32x2 %0, %1, %2, %0;" : "+l"(d) : "l"(a), "l"(b));
}
__device__ __forceinline__ void cp16(uint32_t d, const void* s, int sz) {
    asm volatile("cp.async.cg.shared.global [%0], [%1], 16, %2;\n"
                 :: "r"(d), "l"(s), "r"(sz));
}
__device__ __forceinline__ void ldsm4(uint32_t* r, uint32_t a) {
    asm volatile("ldmatrix.sync.aligned.m8n8.x4.shared.b16 {%0,%1,%2,%3}, [%4];"
                 : "=r"(r[0]), "=r"(r[1]), "=r"(r[2]), "=r"(r[3]) : "r"(a));
}
__device__ __forceinline__ void mma16816(float* d, const uint32_t* a,
                                         uint32_t b0, uint32_t b1) {
    asm volatile("mma.sync.aligned.m16n8k16.row.col.f32.bf16.bf16.f32 "
                 "{%0,%1,%2,%3}, {%4,%5,%6,%7}, {%8,%9}, {%0,%1,%2,%3};"
                 : "+f"(d[0]), "+f"(d[1]), "+f"(d[2]), "+f"(d[3])
                 : "r"(a[0]), "r"(a[1]), "r"(a[2]), "r"(a[3]), "r"(b0), "r"(b1));
}

// ===========================================================================
// Encoder: TRIPLE-buffered fp32 implicit-GEMM conv (wait_group 1).
// BM=128, thread tile 8m x 4n. Per-element accumulation order unchanged
// (taps asc, ic-chunk asc, k asc) -> z is BIT-IDENTICAL to R9/R11/R14.
// ===========================================================================
template<int BN, int IC, int OC, int ACT, int IH, int IW, int OH, int OW,
         int K, int MODE, int S, int P>
__global__ void __launch_bounds__(256, 2)
conv_gemm3(const float* __restrict__ in, const float* __restrict__ w,
           const float* __restrict__ bias, float* __restrict__ out)
{
    constexpr int TN   = BN / 4;
    constexpr int TM   = 256 / TN;
    constexpr int BM   = TM * 8;
    constexpr int PADK = 36;
    constexpr int ICC  = IC / 32;
    constexpr int EOH  = (MODE == 2) ? OH / 2 : OH;
    constexpr int EOW  = (MODE == 2) ? OW / 2 : OW;
    constexpr int LW   = ilog2c(EOW);
    constexpr int LH   = ilog2c(EOH);
    constexpr int NT   = (MODE == 2) ? 4 : K * K;
    constexpr int NIT  = NT * ICC;
    constexpr int LBN4 = ilog2c(BN / 4);

    extern __shared__ char smem[];
    float* sIn = (float*)smem;                 // [3][BM][PADK]
    float* sW  = sIn + 3 * BM * PADK;          // [3][32][BN]
    int*   sIY = (int*)(sW + 3 * 32 * BN);
    int*   sIX = sIY + BM;
    const float** sBase = (const float**)(sIX + BM);

    const int tid  = threadIdx.x;
    const int mblk = blockIdx.x * BM;
    const int ocb  = blockIdx.y * BN;
    int py = 0, px = 0, kpy = 0, kpx = 0;
    if (MODE == 2) {
        py = blockIdx.z >> 1; px = blockIdx.z & 1;
        kpy = (P + py) & 1;   kpx = (P + px) & 1;
    }

    const int tn = tid % TN;
    const int tm = tid / TN;

    if (tid < BM) {
        int m  = mblk + tid;
        int ox = m & (EOW - 1);
        int r1 = m >> LW;
        int oy = r1 & (EOH - 1);
        int n  = r1 >> LH;
        int iy0, ix0;
        if (MODE == 0)      { iy0 = oy * S - P; ix0 = ox * S - P; }
        else if (MODE == 1) { iy0 = oy - P;     ix0 = ox - P; }
        else                { iy0 = oy + ((py + kpy - P) >> 1);
                              ix0 = ox + ((px + kpx - P) >> 1); }
        sIY[tid] = iy0; sIX[tid] = ix0;
        sBase[tid] = in + (size_t)n * IH * IW * IC;
    }
    __syncthreads();

    auto stage = [&](int b, int it) {
        int t   = it / ICC;
        int icb = (it - t * ICC) * 32;
        int ky, kx, dy, dx;
        if (MODE == 2) { int a = t >> 1, e = t & 1; dy = a; dx = e;
                         ky = kpy + 2 * a; kx = kpx + 2 * e; }
        else           { ky = t / K; kx = t - ky * K; dy = ky; dx = kx; }

        uint32_t db = (uint32_t)__cvta_generic_to_shared(sIn + b * (BM * PADK));
#pragma unroll
        for (int u = 0; u < BM / 32; u++) {
            int idx = tid + u * 256;
            int m = idx >> 3, q = idx & 7;
            int iy = sIY[m] + dy, ix = sIX[m] + dx;
            bool v = ((unsigned)iy < (unsigned)IH) && ((unsigned)ix < (unsigned)IW);
            const float* src = v ? (sBase[m] + ((size_t)iy * IW + ix) * IC + icb + q * 4)
                                 : in;
            cp16(db + (uint32_t)((m * PADK + q * 4) * 4), src, v ? 16 : 0);
        }
        uint32_t dw = (uint32_t)__cvta_generic_to_shared(sW + b * (32 * BN));
        const float* wt = w + (size_t)((ky * K + kx) * IC + icb) * OC + ocb;
#pragma unroll
        for (int u = 0; u < BN / 32; u++) {
            int idx = tid + u * 256;
            int r = idx >> LBN4, c4 = idx & (BN / 4 - 1);
            cp16(dw + (uint32_t)((r * BN + c4 * 4) * 4), wt + r * OC + c4 * 4, 16);
        }
    };

    float acc[8][4];
#pragma unroll
    for (int i = 0; i < 8; i++)
#pragma unroll
        for (int j = 0; j < 4; j++) acc[i][j] = 0.0f;

    // prologue: two stages in flight
    stage(0, 0);
    asm volatile("cp.async.commit_group;");
    if (1 < NIT) {
        stage(1, 1);
        asm volatile("cp.async.commit_group;");
    }

    int buf = 0;
    for (int it = 0; it < NIT; ++it) {
        if (it + 1 < NIT)
            asm volatile("cp.async.wait_group 1;");
        else
            asm volatile("cp.async.wait_group 0;");
        __syncthreads();
        if (it + 2 < NIT) {
            int b2 = (it + 2) % 3;
            stage(b2, it + 2);
            asm volatile("cp.async.commit_group;");
        }

        const float* A  = sIn + buf * (BM * PADK) + (tm * 8) * PADK;
        const float* Bw = sW  + buf * (32 * BN) + tn * 4;
#pragma unroll
        for (int kk = 0; kk < 32; kk += 4) {
            float4 b0 = *(const float4*)(Bw + (kk + 0) * BN);
            float4 b1 = *(const float4*)(Bw + (kk + 1) * BN);
            float4 b2 = *(const float4*)(Bw + (kk + 2) * BN);
            float4 b3 = *(const float4*)(Bw + (kk + 3) * BN);
#pragma unroll
            for (int i = 0; i < 8; i++) {
                float4 a = *(const float4*)(A + i * PADK + kk);
                acc[i][0] = fmaf(a.x, b0.x, acc[i][0]);
                acc[i][1] = fmaf(a.x, b0.y, acc[i][1]);
                acc[i][2] = fmaf(a.x, b0.z, acc[i][2]);
                acc[i][3] = fmaf(a.x, b0.w, acc[i][3]);
                acc[i][0] = fmaf(a.y, b1.x, acc[i][0]);
                acc[i][1] = fmaf(a.y, b1.y, acc[i][1]);
                acc[i][2] = fmaf(a.y, b1.z, acc[i][2]);
                acc[i][3] = fmaf(a.y, b1.w, acc[i][3]);
                acc[i][0] = fmaf(a.z, b2.x, acc[i][0]);
                acc[i][1] = fmaf(a.z, b2.y, acc[i][1]);
                acc[i][2] = fmaf(a.z, b2.z, acc[i][2]);
                acc[i][3] = fmaf(a.z, b2.w, acc[i][3]);
                acc[i][0] = fmaf(a.w, b3.x, acc[i][0]);
                acc[i][1] = fmaf(a.w, b3.y, acc[i][1]);
                acc[i][2] = fmaf(a.w, b3.z, acc[i][2]);
                acc[i][3] = fmaf(a.w, b3.w, acc[i][3]);
            }
        }
        buf = (buf + 1 == 3) ? 0 : buf + 1;
    }

    float4 bv = *(const float4*)(bias + ocb + tn * 4);
#pragma unroll
    for (int i = 0; i < 8; i++) {
        int m = mblk + tm * 8 + i;
        size_t off;
        if (MODE == 2) {
            int ox = m & (EOW - 1);
            int r1 = m >> LW;
            int oy = r1 & (EOH - 1);
            int n  = r1 >> LH;
            off = ((size_t)(n * OH + 2 * oy + py) * OW + 2 * ox + px) * OC
                  + ocb + tn * 4;
        } else {
            off = (size_t)m * OC + ocb + tn * 4;
        }
        float4 r;
        r.x = actf(acc[i][0] + bv.x, ACT);
        r.y = actf(acc[i][1] + bv.y, ACT);
        r.z = actf(acc[i][2] + bv.z, ACT);
        r.w = actf(acc[i][3] + bv.w, ACT);
        *(float4*)(out + off) = r;
    }
}

__host__ constexpr int gemm3_smem(int BN) {
    int TM = 256 / (BN / 4);
    int BM = TM * 8;
    return 3 * BM * 36 * 4 + 3 * 32 * BN * 4 + BM * (4 + 4 + 8);
}

// ===========================================================================
// Decoder weight prep: [kk][ic][oc] fp32 -> [oc][kk][ic] bf16 2-split planes
// ===========================================================================
template<int KK, int IC, int OC>
__global__ void wprep(const float* __restrict__ w,
                      __nv_bfloat16* __restrict__ th,
                      __nv_bfloat16* __restrict__ tm)
{
    int i = blockIdx.x * 256 + threadIdx.x;
    if (i >= KK * IC * OC) return;
    int oc = i % OC; int r = i / OC; int ic = r % IC; int kk = r / IC;
    float v = w[i];
    __nv_bfloat16 h = __float2bfloat16(v);
    size_t d = (size_t)oc * (KK * IC) + kk * IC + ic;
    th[d] = h;
    tm[d] = __float2bfloat16(v - __bfloat162float(h));
}

// ===========================================================================
// Decoder: double-buffered tensor-core implicit-GEMM conv, bf16 2-split.
// ===========================================================================
template<int NS, int OSPLIT, int IC, int OC, int ACT, int IH, int IW, int OH,
         int OW, int K, int MODE, int S, int P>
__global__ void __launch_bounds__(256)
conv_tc(const __nv_bfloat16* __restrict__ inH, const __nv_bfloat16* __restrict__ inM,
        const __nv_bfloat16* __restrict__ wH, const __nv_bfloat16* __restrict__ wM,
        const float* __restrict__ bias, float* __restrict__ outF,
        __nv_bfloat16* __restrict__ oH, __nv_bfloat16* __restrict__ oM)
{
    constexpr int EOH = (MODE == 2) ? OH / 2 : OH;
    constexpr int EOW = (MODE == 2) ? OW / 2 : OW;
    constexpr int LW  = ilog2c(EOW), LH = ilog2c(EOH);
    constexpr int NT  = (MODE == 2) ? 4 : K * K;
    constexpr int NST = NT * IC / 64;
    constexpr int LIC = ilog2c(IC);
    constexpr int NF  = OC / 16;
    constexpr int OCB = OC * 128;
    constexpr int ATB = 16384;
    constexpr int BUFB = NS * (ATB + OCB);

    extern __shared__ char smem[];
    int* sOff = (int*)smem;
    int* sIY  = (int*)(smem + 512);
    int* sIX  = (int*)(smem + 1024);
    int* sPix = (int*)(smem + 1536);
    const uint32_t sb0 = (uint32_t)__cvta_generic_to_shared(smem) + 2048;

    const int tid  = threadIdx.x;
    const int lane = tid & 31;
    const int wid  = tid >> 5;
    const int wm   = (wid & 3) * 32;
    const int wn   = (wid >> 2) * (OC / 2);
    const int mblk = blockIdx.x * 128;
    int py = 0, px = 0, kpy = 0, kpx = 0;
    if (MODE == 2) {
        py = blockIdx.z >> 1; px = blockIdx.z & 1;
        kpy = (P + py) & 1;   kpx = (P + px) & 1;
    }

    if (tid < 128) {
        int m  = mblk + tid;
        int ox = m & (EOW - 1);
        int r1 = m >> LW;
        int oy = r1 & (EOH - 1);
        int n  = r1 >> LH;
        int iy0, ix0;
        if (MODE == 0)      { iy0 = oy * S - P; ix0 = ox * S - P; }
        else if (MODE == 1) { iy0 = oy - P;     ix0 = ox - P; }
        else                { iy0 = oy + ((py + kpy - P) >> 1);
                              ix0 = ox + ((px + kpx - P) >> 1); }
        sIY[tid]  = iy0; sIX[tid] = ix0;
        sPix[tid] = n * (IH * IW);
        sOff[tid] = (MODE == 2)
            ? ((n * OH + 2 * oy + py) * OW + 2 * ox + px) * OC
            : m * OC;
    }
    __syncthreads();

    const __nv_bfloat16* inP[2] = {inH, inM};
    const __nv_bfloat16* wP[2]  = {wH, wM};

    auto stage = [&](int b, int st) {
        uint32_t sbA = sb0 + b * BUFB;
        uint32_t sbB = sbA + NS * ATB;
#pragma unroll
        for (int i = tid; i < NS * 1024; i += 256) {
            int s = i >> 10; int r = i & 1023;
            int m = r >> 3;  int pc = r & 7;
            int kg = st * 64 + pc * 8;
            int t  = kg >> LIC;
            int ic0 = kg & (IC - 1);
            int dy, dx;
            if (MODE == 2) { dy = t >> 1; dx = t & 1; }
            else           { dy = t / K;  dx = t % K; }
            int iy = sIY[m] + dy, ix = sIX[m] + dx;
            bool v = ((unsigned)iy < (unsigned)IH) && ((unsigned)ix < (unsigned)IW);
            const __nv_bfloat16* src = v
                ? inP[s] + (((size_t)(sPix[m] + iy * IW + ix)) << LIC) + ic0
                : inP[s];
            uint32_t bo = (uint32_t)((m << 7) + (pc << 4));
            cp16(sbA + s * ATB + (bo ^ ((bo >> 3) & 0x70)), src, v ? 16 : 0);
        }
#pragma unroll
        for (int i = tid; i < NS * OC * 8; i += 256) {
            int s = i / (OC * 8); int r = i % (OC * 8);
            int n = r >> 3; int pc = r & 7;
            int kg = st * 64 + pc * 8;
            int t = kg >> LIC; int ic0 = kg & (IC - 1);
            int kk;
            if (MODE == 2) { int a = t >> 1, e = t & 1;
                             kk = (kpy + 2 * a) * K + (kpx + 2 * e); }
            else kk = t;
            const __nv_bfloat16* src =
                wP[s] + (size_t)n * (K * K * IC) + kk * IC + ic0;
            uint32_t bo = (uint32_t)((n << 7) + (pc << 4));
            cp16(sbB + s * OCB + (bo ^ ((bo >> 3) & 0x70)), src, 16);
        }
    };

    float acc[2][NF][4];
#pragma unroll
    for (int a = 0; a < 2; a++)
#pragma unroll
        for (int b = 0; b < NF; b++)
#pragma unroll
            for (int c = 0; c < 4; c++) acc[a][b][c] = 0.0f;

    int buf = 0;
    stage(0, 0);
    asm volatile("cp.async.commit_group;");

    for (int st = 0; st < NST; st++) {
        asm volatile("cp.async.wait_group 0;");
        __syncthreads();
        if (st + 1 < NST) {
            stage(buf ^ 1, st + 1);
            asm volatile("cp.async.commit_group;");
        }

        uint32_t sbA = sb0 + buf * BUFB;
        uint32_t sbB = sbA + NS * ATB;
#pragma unroll
        for (int ks = 0; ks < 4; ks++) {
#pragma unroll
            for (int pa = 0; pa < NS; pa++) {
                uint32_t af0[4], af1[4];
                {
                    int row0 = wm + (lane & 15);
                    uint32_t apc = (uint32_t)((lane >> 4) << 4);
                    uint32_t bo0 = (uint32_t)(row0 * 128 + ks * 32) + apc;
                    uint32_t bo1 = (uint32_t)((row0 + 16) * 128 + ks * 32) + apc;
                    ldsm4(af0, sbA + pa * ATB + (bo0 ^ ((bo0 >> 3) & 0x70)));
                    ldsm4(af1, sbA + pa * ATB + (bo1 ^ ((bo1 >> 3) & 0x70)));
                }
#pragma unroll
                for (int pb = 0; pb < NS - pa; pb++) {
#pragma unroll
                    for (int j = 0; j < NF / 2; j++) {
                        int n = wn + j * 16 + ((lane >> 4) << 3) + (lane & 7);
                        uint32_t bo = (uint32_t)(n * 128 + ks * 32 +
                                                 (((lane >> 3) & 1) << 4));
                        uint32_t bf[4];
                        ldsm4(bf, sbB + pb * OCB + (bo ^ ((bo >> 3) & 0x70)));
                        mma16816(acc[0][2 * j],     af0, bf[0], bf[1]);
                        mma16816(acc[0][2 * j + 1], af0, bf[2], bf[3]);
                        mma16816(acc[1][2 * j],     af1, bf[0], bf[1]);
                        mma16816(acc[1][2 * j + 1], af1, bf[2], bf[3]);
                    }
                }
            }
        }
        buf ^= 1;
    }

#pragma unroll
    for (int mf = 0; mf < 2; mf++) {
#pragma unroll
        for (int nf = 0; nf < NF; nf++) {
            int col = wn + nf * 8 + ((lane & 3) << 1);
            float2 bv = *(const float2*)(bias + col);
#pragma unroll
            for (int h = 0; h < 2; h++) {
                int row = wm + mf * 16 + (lane >> 2) + h * 8;
                int off = sOff[row] + col;
                float v0 = actf(acc[mf][nf][2 * h]     + bv.x, ACT);
                float v1 = actf(acc[mf][nf][2 * h + 1] + bv.y, ACT);
                if (OSPLIT == 0) {
                    *(float2*)(outF + off) = make_float2(v0, v1);
                } else {
                    __nv_bfloat16 h0 = __float2bfloat16(v0);
                    __nv_bfloat16 h1 = __float2bfloat16(v1);
                    __nv_bfloat162 hh; hh.x = h0; hh.y = h1;
                    __nv_bfloat162 mm;
                    mm.x = __float2bfloat16(v0 - __bfloat162float(h0));
                    mm.y = __float2bfloat16(v1 - __bfloat162float(h1));
                    *(__nv_bfloat162*)(oH + off) = hh;
                    *(__nv_bfloat162*)(oM + off) = mm;
                }
            }
        }
    }
}

__host__ constexpr int tc_smem(int NS, int OC) {
    return 2048 + 2 * NS * (16384 + OC * 128);
}

// ===========================================================================
// enc1: 128x128x3 -> 64x64x32, k4 s2 pad1, relu (fp32 out).
// ===========================================================================
__global__ void __launch_bounds__(256)
enc1_kernel(const float* __restrict__ x, const float* __restrict__ w,
            const float* __restrict__ bias, float* __restrict__ out)
{
    __shared__ float sWgt[1536];
    __shared__ float sX[4 * 396];
    int tid = threadIdx.x;
    int oy = blockIdx.x & 63, n = blockIdx.x >> 6;

#pragma unroll
    for (int u = 0; u < 6; u++) sWgt[tid + u * 256] = w[tid + u * 256];
    for (int j = tid; j < 1584; j += 256) {
        int r = j / 396; int rem = j - r * 396;
        int ixp = rem / 3; int c = rem - ixp * 3;
        int iy = oy * 2 - 1 + r; int ix = ixp - 1;
        float v = 0.0f;
        if ((unsigned)iy < 128u && (unsigned)ix < 128u)
            v = x[((n * 128 + iy) * 128 + ix) * 3 + c];
        sX[j] = v;
    }
    __syncthreads();

    int ox = tid & 63, g = tid >> 6;
    float acc[8];
    float4 b0 = *(const float4*)(bias + g * 8);
    float4 b1 = *(const float4*)(bias + g * 8 + 4);
    acc[0] = b0.x; acc[1] = b0.y; acc[2] = b0.z; acc[3] = b0.w;
    acc[4] = b1.x; acc[5] = b1.y; acc[6] = b1.z; acc[7] = b1.w;

#pragma unroll
    for (int ky = 0; ky < 4; ky++)
#pragma unroll
        for (int kx = 0; kx < 4; kx++)
#pragma unroll
            for (int c = 0; c < 3; c++) {
                float iv = sX[ky * 396 + (ox * 2 + kx) * 3 + c];
                const float* wp = sWgt + ((ky * 4 + kx) * 3 + c) * 32 + g * 8;
                float4 w0 = *(const float4*)wp;
                float4 w1 = *(const float4*)(wp + 4);
                acc[0] = fmaf(iv, w0.x, acc[0]); acc[1] = fmaf(iv, w0.y, acc[1]);
                acc[2] = fmaf(iv, w0.z, acc[2]); acc[3] = fmaf(iv, w0.w, acc[3]);
                acc[4] = fmaf(iv, w1.x, acc[4]); acc[5] = fmaf(iv, w1.y, acc[5]);
                acc[6] = fmaf(iv, w1.z, acc[6]); acc[7] = fmaf(iv, w1.w, acc[7]);
            }

    float* op = out + ((size_t)(n * 64 + oy) * 64 + ox) * 32 + g * 8;
    float4 r0, r1;
    r0.x = fmaxf(acc[0], 0.f); r0.y = fmaxf(acc[1], 0.f);
    r0.z = fmaxf(acc[2], 0.f); r0.w = fmaxf(acc[3], 0.f);
    r1.x = fmaxf(acc[4], 0.f); r1.y = fmaxf(acc[5], 0.f);
    r1.z = fmaxf(acc[6], 0.f); r1.w = fmaxf(acc[7], 0.f);
    *(float4*)op = r0;
    *(float4*)(op + 4) = r1;
}

// ===========================================================================
// dec4: convT 64x64x32 -> 128x128x3, k4 s2 pad_a=2, sigmoid (fp32 in/out).
// ===========================================================================
__global__ void __launch_bounds__(256)
dec4_kernel(const float* __restrict__ in, const float* __restrict__ w,
            const float* __restrict__ bias, float* __restrict__ out)
{
    __shared__ float sw[4][4][3][32];
    int tid = threadIdx.x;
    for (int j = tid; j < 4 * 4 * 32 * 3; j += 256) {
        int c = j % 3; int r = j / 3;
        int ic = r % 32; int kk = r / 32;
        int ky = kk >> 2, kx = kk & 3;
        sw[ky][kx][c][ic] = w[j];
    }
    __syncthreads();

    int t = blockIdx.x * 256 + tid;
    int ox2 = t & 63; int r1 = t >> 6;
    int oy2 = r1 & 63; int n = r1 >> 6;

    float acc[2][2][3];
#pragma unroll
    for (int py = 0; py < 2; py++)
#pragma unroll
        for (int px = 0; px < 2; px++)
#pragma unroll
            for (int c = 0; c < 3; c++) acc[py][px][c] = bias[c];

#pragma unroll
    for (int dy = -1; dy <= 1; dy++) {
        int iy = oy2 + dy;
        if ((unsigned)iy >= 64u) continue;
#pragma unroll
        for (int dx = -1; dx <= 1; dx++) {
            int ix = ox2 + dx;
            if ((unsigned)ix >= 64u) continue;
            const float* ip = in + ((n * 64 + iy) * 64 + ix) * 32;
            float iv[32];
#pragma unroll
            for (int q = 0; q < 8; q++)
                *reinterpret_cast<float4*>(&iv[q * 4]) =
                    *reinterpret_cast<const float4*>(ip + q * 4);
#pragma unroll
            for (int py = 0; py < 2; py++)
#pragma unroll
                for (int a = 0; a < 2; a++) {
                    if (py + a - 1 != dy) continue;
                    int ky = py + 2 * a;
#pragma unroll
                    for (int px = 0; px < 2; px++)
#pragma unroll
                        for (int bq = 0; bq < 2; bq++) {
                            if (px + bq - 1 != dx) continue;
                            int kx = px + 2 * bq;
#pragma unroll
                            for (int c = 0; c < 3; c++)
#pragma unroll
                                for (int ic = 0; ic < 32; ic++)
                                    acc[py][px][c] =
                                        fmaf(iv[ic], sw[ky][kx][c][ic], acc[py][px][c]);
                        }
                }
        }
    }

#pragma unroll
    for (int py = 0; py < 2; py++)
#pragma unroll
        for (int px = 0; px < 2; px++) {
            int base = ((n * 128 + 2 * oy2 + py) * 128 + 2 * ox2 + px) * 3;
#pragma unroll
            for (int c = 0; c < 3; c++)
                out[base + c] = 1.0f / (1.0f + expf(-acc[py][px][c]));
        }
}

// ---------------- VQ ----------------
__global__ void vq_prep(const float* __restrict__ emb)
{
    int k = blockIdx.x * blockDim.x + threadIdx.x;
    if (k == 0) g_loss = 0.0;
    if (k < 512) {
        float s = 0.0f;
#pragma unroll 8
        for (int d = 0; d < 64; d++) { float e = emb[k * 64 + d]; s = fmaf(e, e, s); }
        g_e2[k] = s;
    }
}

// Fused argmin + gather + loss + bf16-split write (z stays in registers).
__global__ void __launch_bounds__(256)
vq_fused(const float* __restrict__ emb)
{
    __shared__ float sE[32 * 64];
    __shared__ float sE2[32];
    int tid = threadIdx.x;
    int p = blockIdx.x * 256 + tid;

    unsigned long long zr[32];
    const float* zp = g_z + p * 64;
#pragma unroll
    for (int q = 0; q < 16; q++) {
        ulonglong2 v = *(const ulonglong2*)(zp + q * 4);
        zr[2 * q] = v.x; zr[2 * q + 1] = v.y;
    }

    float best = 3.4e38f;
    int   bi   = 0;
    for (int kb = 0; kb < 512; kb += 32) {
        __syncthreads();
#pragma unroll
        for (int u = 0; u < 2; u++) {
            int j = tid + u * 256;
            *(float4*)&sE[j * 4] = *(const float4*)(emb + kb * 64 + j * 4);
        }
        if (tid < 32) sE2[tid] = g_e2[kb + tid];
        __syncthreads();
#pragma unroll 2
        for (int k = 0; k < 32; k++) {
            unsigned long long d0 = 0ull, d1 = 0ull, d2 = 0ull, d3 = 0ull;
            const float* ep = &sE[k * 64];
#pragma unroll
            for (int q = 0; q < 8; q++) {
                ulonglong2 e0 = *(const ulonglong2*)(ep + q * 8);
                ulonglong2 e1 = *(const ulonglong2*)(ep + q * 8 + 4);
                ffma2(d0, zr[4 * q + 0], e0.x);
                ffma2(d1, zr[4 * q + 1], e0.y);
                ffma2(d2, zr[4 * q + 2], e1.x);
                ffma2(d3, zr[4 * q + 3], e1.y);
            }
            unsigned long long s0, s1;
            asm("add.rn.f32x2 %0, %1, %2;" : "=l"(s0) : "l"(d0), "l"(d1));
            asm("add.rn.f32x2 %0, %1, %2;" : "=l"(s1) : "l"(d2), "l"(d3));
            asm("add.rn.f32x2 %0, %1, %2;" : "=l"(s0) : "l"(s0), "l"(s1));
            float lo, hi;
            asm("mov.b64 {%0,%1}, %2;" : "=f"(lo), "=f"(hi) : "l"(s0));
            float dist = sE2[k] - 2.0f * (lo + hi);
            if (dist < best) { best = dist; bi = kb + k; }
        }
    }
    g_idx[p] = bi;

    const float* ep = emb + (size_t)bi * 64;
    float sq = 0.0f;
    __align__(16) __nv_bfloat16 hv[64], mv[64];
#pragma unroll
    for (int q = 0; q < 16; q++) {
        float4 e = *(const float4*)(ep + q * 4);
        float z0, z1, z2, z3;
        asm("mov.b64 {%0,%1}, %2;" : "=f"(z0), "=f"(z1) : "l"(zr[2 * q]));
        asm("mov.b64 {%0,%1}, %2;" : "=f"(z2), "=f"(z3) : "l"(zr[2 * q + 1]));
        float dfs[4] = {e.x - z0, e.y - z1, e.z - z2, e.w - z3};
        float qs[4]  = {e.x, e.y, e.z, e.w};
#pragma unroll
        for (int j = 0; j < 4; j++) {
            sq = fmaf(dfs[j], dfs[j], sq);
            __nv_bfloat16 h = __float2bfloat16(qs[j]);
            hv[q * 4 + j] = h;
            mv[q * 4 + j] = __float2bfloat16(qs[j] - __bfloat162float(h));
        }
    }
#pragma unroll
    for (int u = 0; u < 8; u++) {
        *(uint4*)(pqh + (size_t)p * 64 + u * 8) = *(uint4*)&hv[u * 8];
        *(uint4*)(pqm + (size_t)p * 64 + u * 8) = *(uint4*)&mv[u * 8];
    }

#pragma unroll
    for (int o = 16; o > 0; o >>= 1) sq += __shfl_down_sync(0xffffffffu, sq, o);
    __shared__ float sm[8];
    int lane = tid & 31, wid = tid >> 5;
    if (lane == 0) sm[wid] = sq;
    __syncthreads();
    if (wid == 0) {
        float v = (lane < 8) ? sm[lane] : 0.0f;
#pragma unroll
        for (int o = 4; o > 0; o >>= 1) v += __shfl_down_sync(0xffffffffu, v, o);
        if (lane == 0) atomicAdd(&g_loss, (double)v);
    }
}

__global__ void write_tail(float* __restrict__ out, int out_size)
{
    int t = blockIdx.x * blockDim.x + threadIdx.x;
    if (t == 0 && Y_SIZE < out_size)
        out[Y_SIZE] = (float)(0.25 * g_loss / (double)Z_ELEMS);
    int off = Y_SIZE + 1 + t;
    if (t < N_POS && off < out_size)
        out[off] = (float)g_idx[t];
}

// ---------------------------------------------------------------------------
extern "C" void kernel_launch(void* const* d_in, const int* in_sizes, int n_in,
                              void* d_out, int out_size)
{
    const float* x   = (const float*)d_in[0];
    const float* ew1 = (const float*)d_in[1];  const float* eb1 = (const float*)d_in[2];
    const float* ew2 = (const float*)d_in[3];  const float* eb2 = (const float*)d_in[4];
    const float* ew3 = (const float*)d_in[5];  const float* eb3 = (const float*)d_in[6];
    const float* ew4 = (const float*)d_in[7];  const float* eb4 = (const float*)d_in[8];
    const float* emb = (const float*)d_in[9];
    const float* dw1 = (const float*)d_in[10]; const float* db1 = (const float*)d_in[11];
    const float* dw2 = (const float*)d_in[12]; const float* db2 = (const float*)d_in[13];
    const float* dw3 = (const float*)d_in[14]; const float* db3 = (const float*)d_in[15];
    const float* dw4 = (const float*)d_in[16]; const float* db4 = (const float*)d_in[17];
    float* out = (float*)d_out;

    float *a1, *a2, *a3, *zb;
    cudaGetSymbolAddress((void**)&a1, g_a1);
    cudaGetSymbolAddress((void**)&a2, g_a2);
    cudaGetSymbolAddress((void**)&a3, g_a3);
    cudaGetSymbolAddress((void**)&zb, g_z);

    __nv_bfloat16 *Qh, *Qm, *D1h, *D1m, *D2h, *D2m;
    cudaGetSymbolAddress((void**)&Qh, pqh);  cudaGetSymbolAddress((void**)&Qm, pqm);
    cudaGetSymbolAddress((void**)&D1h, d1h); cudaGetSymbolAddress((void**)&D1m, d1m);
    cudaGetSymbolAddress((void**)&D2h, d2h); cudaGetSymbolAddress((void**)&D2m, d2m);

    __nv_bfloat16 *V1h, *V1m, *V2h, *V2m, *V3h, *V3m;
    cudaGetSymbolAddress((void**)&V1h, wd1h); cudaGetSymbolAddress((void**)&V1m, wd1m);
    cudaGetSymbolAddress((void**)&V2h, wd2h); cudaGetSymbolAddress((void**)&V2m, wd2m);
    cudaGetSymbolAddress((void**)&V3h, wd3h); cudaGetSymbolAddress((void**)&V3m, wd3m);

    // encoder (fp32, exact-argmin path, triple-buffered pipeline)
    auto k_enc2 = conv_gemm3<64, 32, 64, ACT_RELU, 64, 64, 32, 32, 4, 0, 2, 1>;
    auto k_enc3 = conv_gemm3<64, 64, 128, ACT_RELU, 32, 32, 16, 16, 4, 0, 2, 1>;
    auto k_enc4 = conv_gemm3<64, 128, 64, ACT_NONE, 16, 16, 16, 16, 2, 0, 1, 0>;
    // decoder (tensor cores, bf16 2-split, double-buffered)
    auto k_dec1 = conv_tc<2, 2, 64, 128, ACT_RELU, 16, 16, 16, 16, 2, 1, 1, 1>;
    auto k_dec2 = conv_tc<2, 2, 128, 64, ACT_RELU, 16, 16, 32, 32, 4, 2, 2, 2>;
    auto k_dec3 = conv_tc<2, 0, 64, 32, ACT_RELU, 32, 32, 64, 64, 4, 2, 2, 2>;

    constexpr int SM64 = gemm3_smem(64);
    constexpr int SM_D1 = tc_smem(2, 128);
    constexpr int SM_D2 = tc_smem(2, 64);
    constexpr int SM_D3 = tc_smem(2, 32);

    cudaFuncSetAttribute(k_enc2, cudaFuncAttributeMaxDynamicSharedMemorySize, SM64);
    cudaFuncSetAttribute(k_enc3, cudaFuncAttributeMaxDynamicSharedMemorySize, SM64);
    cudaFuncSetAttribute(k_enc4, cudaFuncAttributeMaxDynamicSharedMemorySize, SM64);
    cudaFuncSetAttribute(k_dec1, cudaFuncAttributeMaxDynamicSharedMemorySize, SM_D1);
    cudaFuncSetAttribute(k_dec2, cudaFuncAttributeMaxDynamicSharedMemorySize, SM_D2);
    cudaFuncSetAttribute(k_dec3, cudaFuncAttributeMaxDynamicSharedMemorySize, SM_D3);

    // ---- encoder first (so ncu's skip-N capture lands on a heavy kernel) ----
    vq_prep<<<2, 256>>>(emb);
    enc1_kernel<<<128 * 64, 256>>>(x, ew1, eb1, a1);
    k_enc2<<<dim3(1024, 1, 1), 256, SM64>>>(a1, ew2, eb2, a2);
    k_enc3<<<dim3(256, 2, 1), 256, SM64>>>(a2, ew3, eb3, a3);
    k_enc4<<<dim3(256, 1, 1), 256, SM64>>>(a3, ew4, eb4, zb);

    // ---- VQ (fused) ----
    vq_fused<<<N_POS / 256, 256>>>(emb);

    // ---- decoder weight prep (needed only before dec1) ----
    wprep<4, 64, 128><<<128, 256>>>(dw1, V1h, V1m);
    wprep<16, 128, 64><<<512, 256>>>(dw2, V2h, V2m);
    wprep<16, 64, 32><<<128, 256>>>(dw3, V3h, V3m);

    // ---- decoder (tensor cores, double-buffered) ----
    k_dec1<<<dim3(256, 1, 1), 256, SM_D1>>>(Qh, Qm, V1h, V1m, db1,
                                            nullptr, D1h, D1m);
    k_dec2<<<dim3(256, 1, 4), 256, SM_D2>>>(D1h, D1m, V2h, V2m, db2,
                                            nullptr, D2h, D2m);
    k_dec3<<<dim3(1024, 1, 4), 256, SM_D3>>>(D2h, D2m, V3h, V3m, db3,
                                             a1, nullptr, nullptr);
    dec4_kernel<<<128 * 64 * 64 / 256, 256>>>(a1, dw4, db4, out);

    write_tail<<<(N_POS + 255) / 256, 256>>>(out, out_size);
}

// round 16
// speedup vs baseline: 1.1085x; 1.1085x over previous
#include <cuda_runtime.h>
#include <cuda_bf16.h>
#include <math.h>
#include <stdint.h>

#define ACT_NONE 0
#define ACT_RELU 1
#define ACT_SIG  2

// ---------------- fp32 scratch (encoder path + dec3 out) ----------------
__device__ float  g_a1[128 * 64 * 64 * 32];    // enc1 out / dec3 out
__device__ float  g_a2[128 * 32 * 32 * 64];    // enc2 out
__device__ float  g_a3[128 * 16 * 16 * 128];   // enc3 out
__device__ float  g_z [128 * 16 * 16 * 64];
__device__ int    g_idx[128 * 256];
__device__ float  g_e2[512];
__device__ double g_loss;

// ---------------- bf16 split planes (decoder path) ----------------
__device__ __nv_bfloat16 pqh[2097152],  pqm[2097152];   // q
__device__ __nv_bfloat16 d1h[4194304],  d1m[4194304];   // dec1 out
__device__ __nv_bfloat16 d2h[8388608],  d2m[8388608];   // dec2 out
__device__ __nv_bfloat16 wd1h[32768],  wd1m[32768];
__device__ __nv_bfloat16 wd2h[131072], wd2m[131072];
__device__ __nv_bfloat16 wd3h[32768],  wd3m[32768];

static const int Y_SIZE  = 128 * 128 * 128 * 3;
static const int N_POS   = 128 * 16 * 16;
static const int Z_ELEMS = N_POS * 64;

__host__ __device__ constexpr int ilog2c(int v) {
    int l = 0; while (v > 1) { v >>= 1; ++l; } return l;
}

__device__ __forceinline__ float actf(float v, int ACT) {
    if (ACT == ACT_RELU) return fmaxf(v, 0.0f);
    if (ACT == ACT_SIG)  return 1.0f / (1.0f + expf(-v));
    return v;
}

__device__ __forceinline__ void ffma2(unsigned long long& d,
                                      unsigned long long a, unsigned long long b) {
    asm("fma.rn.f32x2 %0, %1, %2, %0;" : "+l"(d) : "l"(a), "l"(b));
}
__device__ __forceinline__ void cp16(uint32_t d, const void* s, int sz) {
    asm volatile("cp.async.cg.shared.global [%0], [%1], 16, %2;\n"
                 :: "r"(d), "l"(s), "r"(sz));
}
__device__ __forceinline__ void ldsm4(uint32_t* r, uint32_t a) {
    asm volatile("ldmatrix.sync.aligned.m8n8.x4.shared.b16 {%0,%1,%2,%3}, [%4];"
                 : "=r"(r[0]), "=r"(r[1]), "=r"(r[2]), "=r"(r[3]) : "r"(a));
}
__device__ __forceinline__ void mma16816(float* d, const uint32_t* a,
                                         uint32_t b0, uint32_t b1) {
    asm volatile("mma.sync.aligned.m16n8k16.row.col.f32.bf16.bf16.f32 "
                 "{%0,%1,%2,%3}, {%4,%5,%6,%7}, {%8,%9}, {%0,%1,%2,%3};"
                 : "+f"(d[0]), "+f"(d[1]), "+f"(d[2]), "+f"(d[3])
                 : "r"(a[0]), "r"(a[1]), "r"(a[2]), "r"(a[3]), "r"(b0), "r"(b1));
}

// ===========================================================================
// Encoder: double-buffered fp32 implicit-GEMM conv (R11/R14 proven config).
// BM=128, thread tile 8m x 4n. z is BIT-IDENTICAL to R9/R11/R14.
// ===========================================================================
template<int BN, int IC, int OC, int ACT, int IH, int IW, int OH, int OW,
         int K, int MODE, int S, int P>
__global__ void __launch_bounds__(256, 2)
conv_gemm3(const float* __restrict__ in, const float* __restrict__ w,
           const float* __restrict__ bias, float* __restrict__ out)
{
    constexpr int TN   = BN / 4;
    constexpr int TM   = 256 / TN;
    constexpr int BM   = TM * 8;
    constexpr int PADK = 36;
    constexpr int ICC  = IC / 32;
    constexpr int EOH  = (MODE == 2) ? OH / 2 : OH;
    constexpr int EOW  = (MODE == 2) ? OW / 2 : OW;
    constexpr int LW   = ilog2c(EOW);
    constexpr int LH   = ilog2c(EOH);
    constexpr int NT   = (MODE == 2) ? 4 : K * K;
    constexpr int NIT  = NT * ICC;
    constexpr int LBN4 = ilog2c(BN / 4);

    extern __shared__ char smem[];
    float* sIn = (float*)smem;
    float* sW  = sIn + 2 * BM * PADK;
    int*   sIY = (int*)(sW + 2 * 32 * BN);
    int*   sIX = sIY + BM;
    const float** sBase = (const float**)(sIX + BM);

    const int tid  = threadIdx.x;
    const int mblk = blockIdx.x * BM;
    const int ocb  = blockIdx.y * BN;
    int py = 0, px = 0, kpy = 0, kpx = 0;
    if (MODE == 2) {
        py = blockIdx.z >> 1; px = blockIdx.z & 1;
        kpy = (P + py) & 1;   kpx = (P + px) & 1;
    }

    const int tn = tid % TN;
    const int tm = tid / TN;

    if (tid < BM) {
        int m  = mblk + tid;
        int ox = m & (EOW - 1);
        int r1 = m >> LW;
        int oy = r1 & (EOH - 1);
        int n  = r1 >> LH;
        int iy0, ix0;
        if (MODE == 0)      { iy0 = oy * S - P; ix0 = ox * S - P; }
        else if (MODE == 1) { iy0 = oy - P;     ix0 = ox - P; }
        else                { iy0 = oy + ((py + kpy - P) >> 1);
                              ix0 = ox + ((px + kpx - P) >> 1); }
        sIY[tid] = iy0; sIX[tid] = ix0;
        sBase[tid] = in + (size_t)n * IH * IW * IC;
    }
    __syncthreads();

    auto stage = [&](int b, int t, int icb) {
        int ky, kx, dy, dx;
        if (MODE == 2) { int a = t >> 1, e = t & 1; dy = a; dx = e;
                         ky = kpy + 2 * a; kx = kpx + 2 * e; }
        else           { ky = t / K; kx = t - ky * K; dy = ky; dx = kx; }

        uint32_t db = (uint32_t)__cvta_generic_to_shared(sIn + b * (BM * PADK));
#pragma unroll
        for (int u = 0; u < BM / 32; u++) {
            int idx = tid + u * 256;
            int m = idx >> 3, q = idx & 7;
            int iy = sIY[m] + dy, ix = sIX[m] + dx;
            bool v = ((unsigned)iy < (unsigned)IH) && ((unsigned)ix < (unsigned)IW);
            const float* src = v ? (sBase[m] + ((size_t)iy * IW + ix) * IC + icb + q * 4)
                                 : in;
            cp16(db + (uint32_t)((m * PADK + q * 4) * 4), src, v ? 16 : 0);
        }
        uint32_t dw = (uint32_t)__cvta_generic_to_shared(sW + b * (32 * BN));
        const float* wt = w + (size_t)((ky * K + kx) * IC + icb) * OC + ocb;
#pragma unroll
        for (int u = 0; u < BN / 32; u++) {
            int idx = tid + u * 256;
            int r = idx >> LBN4, c4 = idx & (BN / 4 - 1);
            cp16(dw + (uint32_t)((r * BN + c4 * 4) * 4), wt + r * OC + c4 * 4, 16);
        }
    };

    float acc[8][4];
#pragma unroll
    for (int i = 0; i < 8; i++)
#pragma unroll
        for (int j = 0; j < 4; j++) acc[i][j] = 0.0f;

    int buf = 0;
    stage(0, 0, 0);
    asm volatile("cp.async.commit_group;");

    for (int it = 0; it < NIT; ++it) {
        asm volatile("cp.async.wait_group 0;");
        __syncthreads();
        if (it + 1 < NIT) {
            int t2   = (it + 1) / ICC;
            int icb2 = ((it + 1) - t2 * ICC) * 32;
            stage(buf ^ 1, t2, icb2);
            asm volatile("cp.async.commit_group;");
        }

        const float* A  = sIn + buf * (BM * PADK) + (tm * 8) * PADK;
        const float* Bw = sW  + buf * (32 * BN) + tn * 4;
#pragma unroll
        for (int kk = 0; kk < 32; kk += 4) {
            float4 b0 = *(const float4*)(Bw + (kk + 0) * BN);
            float4 b1 = *(const float4*)(Bw + (kk + 1) * BN);
            float4 b2 = *(const float4*)(Bw + (kk + 2) * BN);
            float4 b3 = *(const float4*)(Bw + (kk + 3) * BN);
#pragma unroll
            for (int i = 0; i < 8; i++) {
                float4 a = *(const float4*)(A + i * PADK + kk);
                acc[i][0] = fmaf(a.x, b0.x, acc[i][0]);
                acc[i][1] = fmaf(a.x, b0.y, acc[i][1]);
                acc[i][2] = fmaf(a.x, b0.z, acc[i][2]);
                acc[i][3] = fmaf(a.x, b0.w, acc[i][3]);
                acc[i][0] = fmaf(a.y, b1.x, acc[i][0]);
                acc[i][1] = fmaf(a.y, b1.y, acc[i][1]);
                acc[i][2] = fmaf(a.y, b1.z, acc[i][2]);
                acc[i][3] = fmaf(a.y, b1.w, acc[i][3]);
                acc[i][0] = fmaf(a.z, b2.x, acc[i][0]);
                acc[i][1] = fmaf(a.z, b2.y, acc[i][1]);
                acc[i][2] = fmaf(a.z, b2.z, acc[i][2]);
                acc[i][3] = fmaf(a.z, b2.w, acc[i][3]);
                acc[i][0] = fmaf(a.w, b3.x, acc[i][0]);
                acc[i][1] = fmaf(a.w, b3.y, acc[i][1]);
                acc[i][2] = fmaf(a.w, b3.z, acc[i][2]);
                acc[i][3] = fmaf(a.w, b3.w, acc[i][3]);
            }
        }
        buf ^= 1;
    }

    float4 bv = *(const float4*)(bias + ocb + tn * 4);
#pragma unroll
    for (int i = 0; i < 8; i++) {
        int m = mblk + tm * 8 + i;
        size_t off;
        if (MODE == 2) {
            int ox = m & (EOW - 1);
            int r1 = m >> LW;
            int oy = r1 & (EOH - 1);
            int n  = r1 >> LH;
            off = ((size_t)(n * OH + 2 * oy + py) * OW + 2 * ox + px) * OC
                  + ocb + tn * 4;
        } else {
            off = (size_t)m * OC + ocb + tn * 4;
        }
        float4 r;
        r.x = actf(acc[i][0] + bv.x, ACT);
        r.y = actf(acc[i][1] + bv.y, ACT);
        r.z = actf(acc[i][2] + bv.z, ACT);
        r.w = actf(acc[i][3] + bv.w, ACT);
        *(float4*)(out + off) = r;
    }
}

__host__ constexpr int gemm3_smem(int BN) {
    int TM = 256 / (BN / 4);
    int BM = TM * 8;
    return 2 * BM * 36 * 4 + 2 * 32 * BN * 4 + BM * (4 + 4 + 8);
}

// ===========================================================================
// Decoder weight prep: [kk][ic][oc] fp32 -> [oc][kk][ic] bf16 2-split planes
// ===========================================================================
template<int KK, int IC, int OC>
__global__ void wprep(const float* __restrict__ w,
                      __nv_bfloat16* __restrict__ th,
                      __nv_bfloat16* __restrict__ tm)
{
    int i = blockIdx.x * 256 + threadIdx.x;
    if (i >= KK * IC * OC) return;
    int oc = i % OC; int r = i / OC; int ic = r % IC; int kk = r / IC;
    float v = w[i];
    __nv_bfloat16 h = __float2bfloat16(v);
    size_t d = (size_t)oc * (KK * IC) + kk * IC + ic;
    th[d] = h;
    tm[d] = __float2bfloat16(v - __bfloat162float(h));
}

// ===========================================================================
// Decoder: double-buffered tensor-core implicit-GEMM conv, bf16 2-split.
// ===========================================================================
template<int NS, int OSPLIT, int IC, int OC, int ACT, int IH, int IW, int OH,
         int OW, int K, int MODE, int S, int P>
__global__ void __launch_bounds__(256)
conv_tc(const __nv_bfloat16* __restrict__ inH, const __nv_bfloat16* __restrict__ inM,
        const __nv_bfloat16* __restrict__ wH, const __nv_bfloat16* __restrict__ wM,
        const float* __restrict__ bias, float* __restrict__ outF,
        __nv_bfloat16* __restrict__ oH, __nv_bfloat16* __restrict__ oM)
{
    constexpr int EOH = (MODE == 2) ? OH / 2 : OH;
    constexpr int EOW = (MODE == 2) ? OW / 2 : OW;
    constexpr int LW  = ilog2c(EOW), LH = ilog2c(EOH);
    constexpr int NT  = (MODE == 2) ? 4 : K * K;
    constexpr int NST = NT * IC / 64;
    constexpr int LIC = ilog2c(IC);
    constexpr int NF  = OC / 16;
    constexpr int OCB = OC * 128;
    constexpr int ATB = 16384;
    constexpr int BUFB = NS * (ATB + OCB);

    extern __shared__ char smem[];
    int* sOff = (int*)smem;
    int* sIY  = (int*)(smem + 512);
    int* sIX  = (int*)(smem + 1024);
    int* sPix = (int*)(smem + 1536);
    const uint32_t sb0 = (uint32_t)__cvta_generic_to_shared(smem) + 2048;

    const int tid  = threadIdx.x;
    const int lane = tid & 31;
    const int wid  = tid >> 5;
    const int wm   = (wid & 3) * 32;
    const int wn   = (wid >> 2) * (OC / 2);
    const int mblk = blockIdx.x * 128;
    int py = 0, px = 0, kpy = 0, kpx = 0;
    if (MODE == 2) {
        py = blockIdx.z >> 1; px = blockIdx.z & 1;
        kpy = (P + py) & 1;   kpx = (P + px) & 1;
    }

    if (tid < 128) {
        int m  = mblk + tid;
        int ox = m & (EOW - 1);
        int r1 = m >> LW;
        int oy = r1 & (EOH - 1);
        int n  = r1 >> LH;
        int iy0, ix0;
        if (MODE == 0)      { iy0 = oy * S - P; ix0 = ox * S - P; }
        else if (MODE == 1) { iy0 = oy - P;     ix0 = ox - P; }
        else                { iy0 = oy + ((py + kpy - P) >> 1);
                              ix0 = ox + ((px + kpx - P) >> 1); }
        sIY[tid]  = iy0; sIX[tid] = ix0;
        sPix[tid] = n * (IH * IW);
        sOff[tid] = (MODE == 2)
            ? ((n * OH + 2 * oy + py) * OW + 2 * ox + px) * OC
            : m * OC;
    }
    __syncthreads();

    const __nv_bfloat16* inP[2] = {inH, inM};
    const __nv_bfloat16* wP[2]  = {wH, wM};

    auto stage = [&](int b, int st) {
        uint32_t sbA = sb0 + b * BUFB;
        uint32_t sbB = sbA + NS * ATB;
#pragma unroll
        for (int i = tid; i < NS * 1024; i += 256) {
            int s = i >> 10; int r = i & 1023;
            int m = r >> 3;  int pc = r & 7;
            int kg = st * 64 + pc * 8;
            int t  = kg >> LIC;
            int ic0 = kg & (IC - 1);
            int dy, dx;
            if (MODE == 2) { dy = t >> 1; dx = t & 1; }
            else           { dy = t / K;  dx = t % K; }
            int iy = sIY[m] + dy, ix = sIX[m] + dx;
            bool v = ((unsigned)iy < (unsigned)IH) && ((unsigned)ix < (unsigned)IW);
            const __nv_bfloat16* src = v
                ? inP[s] + (((size_t)(sPix[m] + iy * IW + ix)) << LIC) + ic0
                : inP[s];
            uint32_t bo = (uint32_t)((m << 7) + (pc << 4));
            cp16(sbA + s * ATB + (bo ^ ((bo >> 3) & 0x70)), src, v ? 16 : 0);
        }
#pragma unroll
        for (int i = tid; i < NS * OC * 8; i += 256) {
            int s = i / (OC * 8); int r = i % (OC * 8);
            int n = r >> 3; int pc = r & 7;
            int kg = st * 64 + pc * 8;
            int t = kg >> LIC; int ic0 = kg & (IC - 1);
            int kk;
            if (MODE == 2) { int a = t >> 1, e = t & 1;
                             kk = (kpy + 2 * a) * K + (kpx + 2 * e); }
            else kk = t;
            const __nv_bfloat16* src =
                wP[s] + (size_t)n * (K * K * IC) + kk * IC + ic0;
            uint32_t bo = (uint32_t)((n << 7) + (pc << 4));
            cp16(sbB + s * OCB + (bo ^ ((bo >> 3) & 0x70)), src, 16);
        }
    };

    float acc[2][NF][4];
#pragma unroll
    for (int a = 0; a < 2; a++)
#pragma unroll
        for (int b = 0; b < NF; b++)
#pragma unroll
            for (int c = 0; c < 4; c++) acc[a][b][c] = 0.0f;

    int buf = 0;
    stage(0, 0);
    asm volatile("cp.async.commit_group;");

    for (int st = 0; st < NST; st++) {
        asm volatile("cp.async.wait_group 0;");
        __syncthreads();
        if (st + 1 < NST) {
            stage(buf ^ 1, st + 1);
            asm volatile("cp.async.commit_group;");
        }

        uint32_t sbA = sb0 + buf * BUFB;
        uint32_t sbB = sbA + NS * ATB;
#pragma unroll
        for (int ks = 0; ks < 4; ks++) {
#pragma unroll
            for (int pa = 0; pa < NS; pa++) {
                uint32_t af0[4], af1[4];
                {
                    int row0 = wm + (lane & 15);
                    uint32_t apc = (uint32_t)((lane >> 4) << 4);
                    uint32_t bo0 = (uint32_t)(row0 * 128 + ks * 32) + apc;
                    uint32_t bo1 = (uint32_t)((row0 + 16) * 128 + ks * 32) + apc;
                    ldsm4(af0, sbA + pa * ATB + (bo0 ^ ((bo0 >> 3) & 0x70)));
                    ldsm4(af1, sbA + pa * ATB + (bo1 ^ ((bo1 >> 3) & 0x70)));
                }
#pragma unroll
                for (int pb = 0; pb < NS - pa; pb++) {
#pragma unroll
                    for (int j = 0; j < NF / 2; j++) {
                        int n = wn + j * 16 + ((lane >> 4) << 3) + (lane & 7);
                        uint32_t bo = (uint32_t)(n * 128 + ks * 32 +
                                                 (((lane >> 3) & 1) << 4));
                        uint32_t bf[4];
                        ldsm4(bf, sbB + pb * OCB + (bo ^ ((bo >> 3) & 0x70)));
                        mma16816(acc[0][2 * j],     af0, bf[0], bf[1]);
                        mma16816(acc[0][2 * j + 1], af0, bf[2], bf[3]);
                        mma16816(acc[1][2 * j],     af1, bf[0], bf[1]);
                        mma16816(acc[1][2 * j + 1], af1, bf[2], bf[3]);
                    }
                }
            }
        }
        buf ^= 1;
    }

#pragma unroll
    for (int mf = 0; mf < 2; mf++) {
#pragma unroll
        for (int nf = 0; nf < NF; nf++) {
            int col = wn + nf * 8 + ((lane & 3) << 1);
            float2 bv = *(const float2*)(bias + col);
#pragma unroll
            for (int h = 0; h < 2; h++) {
                int row = wm + mf * 16 + (lane >> 2) + h * 8;
                int off = sOff[row] + col;
                float v0 = actf(acc[mf][nf][2 * h]     + bv.x, ACT);
                float v1 = actf(acc[mf][nf][2 * h + 1] + bv.y, ACT);
                if (OSPLIT == 0) {
                    *(float2*)(outF + off) = make_float2(v0, v1);
                } else {
                    __nv_bfloat16 h0 = __float2bfloat16(v0);
                    __nv_bfloat16 h1 = __float2bfloat16(v1);
                    __nv_bfloat162 hh; hh.x = h0; hh.y = h1;
                    __nv_bfloat162 mm;
                    mm.x = __float2bfloat16(v0 - __bfloat162float(h0));
                    mm.y = __float2bfloat16(v1 - __bfloat162float(h1));
                    *(__nv_bfloat162*)(oH + off) = hh;
                    *(__nv_bfloat162*)(oM + off) = mm;
                }
            }
        }
    }
}

__host__ constexpr int tc_smem(int NS, int OC) {
    return 2048 + 2 * NS * (16384 + OC * 128);
}

// ===========================================================================
// enc1: 128x128x3 -> 64x64x32, k4 s2 pad1, relu (fp32 out).
// ===========================================================================
__global__ void __launch_bounds__(256)
enc1_kernel(const float* __restrict__ x, const float* __restrict__ w,
            const float* __restrict__ bias, float* __restrict__ out)
{
    __shared__ float sWgt[1536];
    __shared__ float sX[4 * 396];
    int tid = threadIdx.x;
    int oy = blockIdx.x & 63, n = blockIdx.x >> 6;

#pragma unroll
    for (int u = 0; u < 6; u++) sWgt[tid + u * 256] = w[tid + u * 256];
    for (int j = tid; j < 1584; j += 256) {
        int r = j / 396; int rem = j - r * 396;
        int ixp = rem / 3; int c = rem - ixp * 3;
        int iy = oy * 2 - 1 + r; int ix = ixp - 1;
        float v = 0.0f;
        if ((unsigned)iy < 128u && (unsigned)ix < 128u)
            v = x[((n * 128 + iy) * 128 + ix) * 3 + c];
        sX[j] = v;
    }
    __syncthreads();

    int ox = tid & 63, g = tid >> 6;
    float acc[8];
    float4 b0 = *(const float4*)(bias + g * 8);
    float4 b1 = *(const float4*)(bias + g * 8 + 4);
    acc[0] = b0.x; acc[1] = b0.y; acc[2] = b0.z; acc[3] = b0.w;
    acc[4] = b1.x; acc[5] = b1.y; acc[6] = b1.z; acc[7] = b1.w;

#pragma unroll
    for (int ky = 0; ky < 4; ky++)
#pragma unroll
        for (int kx = 0; kx < 4; kx++)
#pragma unroll
            for (int c = 0; c < 3; c++) {
                float iv = sX[ky * 396 + (ox * 2 + kx) * 3 + c];
                const float* wp = sWgt + ((ky * 4 + kx) * 3 + c) * 32 + g * 8;
                float4 w0 = *(const float4*)wp;
                float4 w1 = *(const float4*)(wp + 4);
                acc[0] = fmaf(iv, w0.x, acc[0]); acc[1] = fmaf(iv, w0.y, acc[1]);
                acc[2] = fmaf(iv, w0.z, acc[2]); acc[3] = fmaf(iv, w0.w, acc[3]);
                acc[4] = fmaf(iv, w1.x, acc[4]); acc[5] = fmaf(iv, w1.y, acc[5]);
                acc[6] = fmaf(iv, w1.z, acc[6]); acc[7] = fmaf(iv, w1.w, acc[7]);
            }

    float* op = out + ((size_t)(n * 64 + oy) * 64 + ox) * 32 + g * 8;
    float4 r0, r1;
    r0.x = fmaxf(acc[0], 0.f); r0.y = fmaxf(acc[1], 0.f);
    r0.z = fmaxf(acc[2], 0.f); r0.w = fmaxf(acc[3], 0.f);
    r1.x = fmaxf(acc[4], 0.f); r1.y = fmaxf(acc[5], 0.f);
    r1.z = fmaxf(acc[6], 0.f); r1.w = fmaxf(acc[7], 0.f);
    *(float4*)op = r0;
    *(float4*)(op + 4) = r1;
}

// ===========================================================================
// dec4: convT 64x64x32 -> 128x128x3, k4 s2 pad_a=2, sigmoid.
// SMEM-TILED: block = 16x16 input tile (+1 halo), staged once via cp.async
// with zero-fill. Channels-inner layout padded to 36 (16B-aligned, 2-way
// conflict max). Halo zeros contribute exact fmaf(0,w,acc)=acc -> y is
// bit-identical to the previous global-load version.
// ===========================================================================
__global__ void __launch_bounds__(256)
dec4_kernel(const float* __restrict__ in, const float* __restrict__ w,
            const float* __restrict__ bias, float* __restrict__ out)
{
    __shared__ float sw[4][4][3][32];
    extern __shared__ float sX[];     // [18][18][36]

    int tid = threadIdx.x;
    int blk = blockIdx.x;             // n*16 + ty*4 + tx
    int tx = blk & 3;
    int ty = (blk >> 2) & 3;
    int n  = blk >> 4;
    int oy0 = ty * 16, ox0 = tx * 16;

    // weights -> smem (same order as before)
    for (int j = tid; j < 4 * 4 * 32 * 3; j += 256) {
        int c = j % 3; int r = j / 3;
        int ic = r % 32; int kk = r / 32;
        int ky = kk >> 2, kx = kk & 3;
        sw[ky][kx][c][ic] = w[j];
    }

    // stage 18x18x32 input tile (zero halo) via cp.async
    {
        const float* base = in + (size_t)n * 64 * 64 * 32;
        uint32_t db = (uint32_t)__cvta_generic_to_shared(sX);
        for (int j = tid; j < 18 * 18 * 8; j += 256) {
            int q = j & 7; int pos = j >> 3;
            int lx = pos % 18; int ly = pos / 18;
            int iy = oy0 - 1 + ly, ix = ox0 - 1 + lx;
            bool v = ((unsigned)iy < 64u) && ((unsigned)ix < 64u);
            const float* src = v ? (base + ((size_t)(iy * 64 + ix) * 32 + q * 4))
                                 : in;
            cp16(db + (uint32_t)(((ly * 18 + lx) * 36 + q * 4) * 4), src,
                 v ? 16 : 0);
        }
        asm volatile("cp.async.commit_group;");
        asm volatile("cp.async.wait_group 0;");
    }
    __syncthreads();

    int lx2 = tid & 15, ly2 = tid >> 4;
    int ox2 = ox0 + lx2, oy2 = oy0 + ly2;

    float acc[2][2][3];
#pragma unroll
    for (int py = 0; py < 2; py++)
#pragma unroll
        for (int px = 0; px < 2; px++)
#pragma unroll
            for (int c = 0; c < 3; c++) acc[py][px][c] = bias[c];

#pragma unroll
    for (int dy = -1; dy <= 1; dy++) {
#pragma unroll
        for (int dx = -1; dx <= 1; dx++) {
            const float* ip = &sX[((ly2 + 1 + dy) * 18 + (lx2 + 1 + dx)) * 36];
            float iv[32];
#pragma unroll
            for (int q = 0; q < 8; q++)
                *reinterpret_cast<float4*>(&iv[q * 4]) =
                    *reinterpret_cast<const float4*>(ip + q * 4);
#pragma unroll
            for (int py = 0; py < 2; py++)
#pragma unroll
                for (int a = 0; a < 2; a++) {
                    if (py + a - 1 != dy) continue;
                    int ky = py + 2 * a;
#pragma unroll
                    for (int px = 0; px < 2; px++)
#pragma unroll
                        for (int bq = 0; bq < 2; bq++) {
                            if (px + bq - 1 != dx) continue;
                            int kx = px + 2 * bq;
#pragma unroll
                            for (int c = 0; c < 3; c++)
#pragma unroll
                                for (int ic = 0; ic < 32; ic++)
                                    acc[py][px][c] =
                                        fmaf(iv[ic], sw[ky][kx][c][ic], acc[py][px][c]);
                        }
                }
        }
    }

#pragma unroll
    for (int py = 0; py < 2; py++)
#pragma unroll
        for (int px = 0; px < 2; px++) {
            int base = ((n * 128 + 2 * oy2 + py) * 128 + 2 * ox2 + px) * 3;
#pragma unroll
            for (int c = 0; c < 3; c++)
                out[base + c] = 1.0f / (1.0f + expf(-acc[py][px][c]));
        }
}

static const int DEC4_SMEM = 18 * 18 * 36 * 4;   // 46656 bytes dynamic

// ---------------- VQ ----------------
__global__ void vq_prep(const float* __restrict__ emb)
{
    int k = blockIdx.x * blockDim.x + threadIdx.x;
    if (k == 0) g_loss = 0.0;
    if (k < 512) {
        float s = 0.0f;
#pragma unroll 8
        for (int d = 0; d < 64; d++) { float e = emb[k * 64 + d]; s = fmaf(e, e, s); }
        g_e2[k] = s;
    }
}

// Fused argmin + gather + loss + bf16-split write (z stays in registers).
__global__ void __launch_bounds__(256)
vq_fused(const float* __restrict__ emb)
{
    __shared__ float sE[32 * 64];
    __shared__ float sE2[32];
    int tid = threadIdx.x;
    int p = blockIdx.x * 256 + tid;

    unsigned long long zr[32];
    const float* zp = g_z + p * 64;
#pragma unroll
    for (int q = 0; q < 16; q++) {
        ulonglong2 v = *(const ulonglong2*)(zp + q * 4);
        zr[2 * q] = v.x; zr[2 * q + 1] = v.y;
    }

    float best = 3.4e38f;
    int   bi   = 0;
    for (int kb = 0; kb < 512; kb += 32) {
        __syncthreads();
#pragma unroll
        for (int u = 0; u < 2; u++) {
            int j = tid + u * 256;
            *(float4*)&sE[j * 4] = *(const float4*)(emb + kb * 64 + j * 4);
        }
        if (tid < 32) sE2[tid] = g_e2[kb + tid];
        __syncthreads();
#pragma unroll 2
        for (int k = 0; k < 32; k++) {
            unsigned long long d0 = 0ull, d1 = 0ull, d2 = 0ull, d3 = 0ull;
            const float* ep = &sE[k * 64];
#pragma unroll
            for (int q = 0; q < 8; q++) {
                ulonglong2 e0 = *(const ulonglong2*)(ep + q * 8);
                ulonglong2 e1 = *(const ulonglong2*)(ep + q * 8 + 4);
                ffma2(d0, zr[4 * q + 0], e0.x);
                ffma2(d1, zr[4 * q + 1], e0.y);
                ffma2(d2, zr[4 * q + 2], e1.x);
                ffma2(d3, zr[4 * q + 3], e1.y);
            }
            unsigned long long s0, s1;
            asm("add.rn.f32x2 %0, %1, %2;" : "=l"(s0) : "l"(d0), "l"(d1));
            asm("add.rn.f32x2 %0, %1, %2;" : "=l"(s1) : "l"(d2), "l"(d3));
            asm("add.rn.f32x2 %0, %1, %2;" : "=l"(s0) : "l"(s0), "l"(s1));
            float lo, hi;
            asm("mov.b64 {%0,%1}, %2;" : "=f"(lo), "=f"(hi) : "l"(s0));
            float dist = sE2[k] - 2.0f * (lo + hi);
            if (dist < best) { best = dist; bi = kb + k; }
        }
    }
    g_idx[p] = bi;

    const float* ep = emb + (size_t)bi * 64;
    float sq = 0.0f;
    __align__(16) __nv_bfloat16 hv[64], mv[64];
#pragma unroll
    for (int q = 0; q < 16; q++) {
        float4 e = *(const float4*)(ep + q * 4);
        float z0, z1, z2, z3;
        asm("mov.b64 {%0,%1}, %2;" : "=f"(z0), "=f"(z1) : "l"(zr[2 * q]));
        asm("mov.b64 {%0,%1}, %2;" : "=f"(z2), "=f"(z3) : "l"(zr[2 * q + 1]));
        float dfs[4] = {e.x - z0, e.y - z1, e.z - z2, e.w - z3};
        float qs[4]  = {e.x, e.y, e.z, e.w};
#pragma unroll
        for (int j = 0; j < 4; j++) {
            sq = fmaf(dfs[j], dfs[j], sq);
            __nv_bfloat16 h = __float2bfloat16(qs[j]);
            hv[q * 4 + j] = h;
            mv[q * 4 + j] = __float2bfloat16(qs[j] - __bfloat162float(h));
        }
    }
#pragma unroll
    for (int u = 0; u < 8; u++) {
        *(uint4*)(pqh + (size_t)p * 64 + u * 8) = *(uint4*)&hv[u * 8];
        *(uint4*)(pqm + (size_t)p * 64 + u * 8) = *(uint4*)&mv[u * 8];
    }

#pragma unroll
    for (int o = 16; o > 0; o >>= 1) sq += __shfl_down_sync(0xffffffffu, sq, o);
    __shared__ float sm[8];
    int lane = tid & 31, wid = tid >> 5;
    if (lane == 0) sm[wid] = sq;
    __syncthreads();
    if (wid == 0) {
        float v = (lane < 8) ? sm[lane] : 0.0f;
#pragma unroll
        for (int o = 4; o > 0; o >>= 1) v += __shfl_down_sync(0xffffffffu, v, o);
        if (lane == 0) atomicAdd(&g_loss, (double)v);
    }
}

__global__ void write_tail(float* __restrict__ out, int out_size)
{
    int t = blockIdx.x * blockDim.x + threadIdx.x;
    if (t == 0 && Y_SIZE < out_size)
        out[Y_SIZE] = (float)(0.25 * g_loss / (double)Z_ELEMS);
    int off = Y_SIZE + 1 + t;
    if (t < N_POS && off < out_size)
        out[off] = (float)g_idx[t];
}

// ---------------------------------------------------------------------------
extern "C" void kernel_launch(void* const* d_in, const int* in_sizes, int n_in,
                              void* d_out, int out_size)
{
    const float* x   = (const float*)d_in[0];
    const float* ew1 = (const float*)d_in[1];  const float* eb1 = (const float*)d_in[2];
    const float* ew2 = (const float*)d_in[3];  const float* eb2 = (const float*)d_in[4];
    const float* ew3 = (const float*)d_in[5];  const float* eb3 = (const float*)d_in[6];
    const float* ew4 = (const float*)d_in[7];  const float* eb4 = (const float*)d_in[8];
    const float* emb = (const float*)d_in[9];
    const float* dw1 = (const float*)d_in[10]; const float* db1 = (const float*)d_in[11];
    const float* dw2 = (const float*)d_in[12]; const float* db2 = (const float*)d_in[13];
    const float* dw3 = (const float*)d_in[14]; const float* db3 = (const float*)d_in[15];
    const float* dw4 = (const float*)d_in[16]; const float* db4 = (const float*)d_in[17];
    float* out = (float*)d_out;

    float *a1, *a2, *a3, *zb;
    cudaGetSymbolAddress((void**)&a1, g_a1);
    cudaGetSymbolAddress((void**)&a2, g_a2);
    cudaGetSymbolAddress((void**)&a3, g_a3);
    cudaGetSymbolAddress((void**)&zb, g_z);

    __nv_bfloat16 *Qh, *Qm, *D1h, *D1m, *D2h, *D2m;
    cudaGetSymbolAddress((void**)&Qh, pqh);  cudaGetSymbolAddress((void**)&Qm, pqm);
    cudaGetSymbolAddress((void**)&D1h, d1h); cudaGetSymbolAddress((void**)&D1m, d1m);
    cudaGetSymbolAddress((void**)&D2h, d2h); cudaGetSymbolAddress((void**)&D2m, d2m);

    __nv_bfloat16 *V1h, *V1m, *V2h, *V2m, *V3h, *V3m;
    cudaGetSymbolAddress((void**)&V1h, wd1h); cudaGetSymbolAddress((void**)&V1m, wd1m);
    cudaGetSymbolAddress((void**)&V2h, wd2h); cudaGetSymbolAddress((void**)&V2m, wd2m);
    cudaGetSymbolAddress((void**)&V3h, wd3h); cudaGetSymbolAddress((void**)&V3m, wd3m);

    // encoder (fp32, exact-argmin path, R14 double-buffered config)
    auto k_enc2 = conv_gemm3<64, 32, 64, ACT_RELU, 64, 64, 32, 32, 4, 0, 2, 1>;
    auto k_enc3 = conv_gemm3<64, 64, 128, ACT_RELU, 32, 32, 16, 16, 4, 0, 2, 1>;
    auto k_enc4 = conv_gemm3<64, 128, 64, ACT_NONE, 16, 16, 16, 16, 2, 0, 1, 0>;
    // decoder (tensor cores, bf16 2-split, double-buffered)
    auto k_dec1 = conv_tc<2, 2, 64, 128, ACT_RELU, 16, 16, 16, 16, 2, 1, 1, 1>;
    auto k_dec2 = conv_tc<2, 2, 128, 64, ACT_RELU, 16, 16, 32, 32, 4, 2, 2, 2>;
    auto k_dec3 = conv_tc<2, 0, 64, 32, ACT_RELU, 32, 32, 64, 64, 4, 2, 2, 2>;

    constexpr int SM64 = gemm3_smem(64);
    constexpr int SM_D1 = tc_smem(2, 128);
    constexpr int SM_D2 = tc_smem(2, 64);
    constexpr int SM_D3 = tc_smem(2, 32);

    cudaFuncSetAttribute(k_enc2, cudaFuncAttributeMaxDynamicSharedMemorySize, SM64);
    cudaFuncSetAttribute(k_enc3, cudaFuncAttributeMaxDynamicSharedMemorySize, SM64);
    cudaFuncSetAttribute(k_enc4, cudaFuncAttributeMaxDynamicSharedMemorySize, SM64);
    cudaFuncSetAttribute(k_dec1, cudaFuncAttributeMaxDynamicSharedMemorySize, SM_D1);
    cudaFuncSetAttribute(k_dec2, cudaFuncAttributeMaxDynamicSharedMemorySize, SM_D2);
    cudaFuncSetAttribute(k_dec3, cudaFuncAttributeMaxDynamicSharedMemorySize, SM_D3);
    cudaFuncSetAttribute(dec4_kernel, cudaFuncAttributeMaxDynamicSharedMemorySize,
                         DEC4_SMEM);

    // ---- encoder first (keeps enc3 in ncu's capture slot) ----
    vq_prep<<<2, 256>>>(emb);
    enc1_kernel<<<128 * 64, 256>>>(x, ew1, eb1, a1);
    k_enc2<<<dim3(1024, 1, 1), 256, SM64>>>(a1, ew2, eb2, a2);
    k_enc3<<<dim3(256, 2, 1), 256, SM64>>>(a2, ew3, eb3, a3);
    k_enc4<<<dim3(256, 1, 1), 256, SM64>>>(a3, ew4, eb4, zb);

    // ---- VQ (fused) ----
    vq_fused<<<N_POS / 256, 256>>>(emb);

    // ---- decoder weight prep ----
    wprep<4, 64, 128><<<128, 256>>>(dw1, V1h, V1m);
    wprep<16, 128, 64><<<512, 256>>>(dw2, V2h, V2m);
    wprep<16, 64, 32><<<128, 256>>>(dw3, V3h, V3m);

    // ---- decoder ----
    k_dec1<<<dim3(256, 1, 1), 256, SM_D1>>>(Qh, Qm, V1h, V1m, db1,
                                            nullptr, D1h, D1m);
    k_dec2<<<dim3(256, 1, 4), 256, SM_D2>>>(D1h, D1m, V2h, V2m, db2,
                                            nullptr, D2h, D2m);
    k_dec3<<<dim3(1024, 1, 4), 256, SM_D3>>>(D2h, D2m, V3h, V3m, db3,
                                             a1, nullptr, nullptr);
    dec4_kernel<<<2048, 256, DEC4_SMEM>>>(a1, dw4, db4, out);

    write_tail<<<(N_POS + 255) / 256, 256>>>(out, out_size);
}